// round 1
// baseline (speedup 1.0000x reference)
#include <cuda_runtime.h>
#include <cuda_bf16.h>

#define MARGIN 1.0f
#define WARPS_PER_BLOCK 8
#define THREADS_PER_BLOCK (WARPS_PER_BLOCK * 32)

// C = 1000 floats per row = 250 float4 per row (4000 bytes, 16B aligned rows)
#define C_CLASSES 1000
#define C_VEC4 250   // 1000 / 4

__global__ void hinge_init_kernel(float* out) {
    if (threadIdx.x == 0 && blockIdx.x == 0) out[0] = 0.0f;
}

__global__ __launch_bounds__(THREADS_PER_BLOCK)
void hinge_main_kernel(const float* __restrict__ pred,
                       const long long* __restrict__ target,
                       float* __restrict__ out,
                       int B, float inv_B) {
    const int warp_id = threadIdx.x >> 5;
    const int lane    = threadIdx.x & 31;
    const int row     = blockIdx.x * WARPS_PER_BLOCK + warp_id;

    __shared__ float s_partial[WARPS_PER_BLOCK];

    float hinge = 0.0f;
    if (row < B) {
        const long long t = target[row];               // target class index
        const int t_vec   = (int)(t >> 2);             // which float4 holds it
        const int t_sub   = (int)(t & 3);              // which component
        const int t_lane  = t_vec & 31;                // lane that owns that float4

        const float4* rowp = (const float4*)(pred + (size_t)row * C_CLASSES);

        float vmax = -3.4e38f;   // max over j != target
        float corr = 0.0f;       // p_target (valid only on t_lane)

        // 250 float4 per row, 32 lanes -> iterations 0..7 (last partial)
        #pragma unroll
        for (int i = 0; i < 8; i++) {
            const int f = lane + (i << 5);
            if (f < C_VEC4) {
                float4 v = __ldg(&rowp[f]);
                if (f == t_vec) {
                    // extract correct-class value, mask it out of the max
                    float vals[4] = {v.x, v.y, v.z, v.w};
                    corr = vals[t_sub];
                    vals[t_sub] = -3.4e38f;
                    vmax = fmaxf(vmax, fmaxf(fmaxf(vals[0], vals[1]),
                                             fmaxf(vals[2], vals[3])));
                } else {
                    vmax = fmaxf(vmax, fmaxf(fmaxf(v.x, v.y), fmaxf(v.z, v.w)));
                }
            }
        }

        // warp max-reduce
        #pragma unroll
        for (int off = 16; off > 0; off >>= 1)
            vmax = fmaxf(vmax, __shfl_xor_sync(0xFFFFFFFFu, vmax, off));

        // broadcast correct-class value from its owning lane
        corr = __shfl_sync(0xFFFFFFFFu, corr, t_lane);

        hinge = fmaxf(vmax - corr + MARGIN, 0.0f);
    }

    if (lane == 0) s_partial[warp_id] = hinge;
    __syncthreads();

    // block reduce (8 values) on warp 0
    if (warp_id == 0) {
        float s = (lane < WARPS_PER_BLOCK) ? s_partial[lane] : 0.0f;
        #pragma unroll
        for (int off = 4; off > 0; off >>= 1)
            s += __shfl_xor_sync(0xFFFFFFFFu, s, off);
        if (lane == 0) atomicAdd(out, s * inv_B);
    }
}

extern "C" void kernel_launch(void* const* d_in, const int* in_sizes, int n_in,
                              void* d_out, int out_size) {
    const float*     pred   = (const float*)d_in[0];
    const long long* target = (const long long*)d_in[1];
    float*           out    = (float*)d_out;

    const int B = in_sizes[1];          // target has B elements
    const float inv_B = 1.0f / (float)B;

    hinge_init_kernel<<<1, 32>>>(out);

    const int blocks = (B + WARPS_PER_BLOCK - 1) / WARPS_PER_BLOCK;
    hinge_main_kernel<<<blocks, THREADS_PER_BLOCK>>>(pred, target, out, B, inv_B);
}